// round 1
// baseline (speedup 1.0000x reference)
#include <cuda_runtime.h>
#include <math.h>

// ---------------- problem constants ----------------
#define PP   25        // train samples (way*shot)
#define QQ   2000      // test samples (way*query)
#define CC   640       // channels
#define SS   25        // spatial (5x5)
#define TILE 16000     // CC*SS floats per sample
#define WAY  5

// output layout: [ftrain_out 400000][ftest_out 32000000][am 50000][cls 10000]
#define OFT_TE  400000
#define OFT_AM  32400000
#define OFT_CLS 32450000

// ---------------- device scratch (static, no allocation) ----------------
__device__ float g_Ag[PP * TILE];        // normalized ftrain [p][c][hw]
__device__ float g_Abar[PP * CC];        // mean over hw of A
__device__ float g_ntinv[QQ * SS];       // 1/norm for ftest per (q,xy)
__device__ float g_Bbar[QQ * CC];        // mean over xy of normalized ftest
__device__ float g_att1[PP * QQ * SS];   // att1[p][q][xy]

// ---------------- smem layout for main kernel (floats) ----------------
#define O_BS   0
#define O_AS   16000
#define O_BBAR 32000
#define O_ABAR 32640
#define O_U    33280
#define O_V    33920
#define O_G1   34560
#define O_G2   34585
#define O_K1   34610
#define O_K2   34635
#define O_ATT  34660
#define O_AM   34685
#define O_H1A  34710
#define O_H1B  34715
#define O_CLS  34720
#define O_SC   34725
#define O_B1F  34730
#define O_W1F  34735
#define O_W2   34860
#define O_B2   34985
#define SM_FLOATS 35010
#define SM_BYTES (SM_FLOATS * 4)

__device__ __forceinline__ float warp_sum(float v) {
    #pragma unroll
    for (int o = 16; o; o >>= 1) v += __shfl_xor_sync(0xffffffffu, v, o);
    return v;
}

// ---------------- K1: normalize ftrain, store A + Abar ----------------
__global__ void __launch_bounds__(256) cam_prep_train(const float* __restrict__ ftrain) {
    extern __shared__ float sm[];
    float* xs    = sm;          // 16000
    float* inv_s = sm + 16000;  // 25
    int p = blockIdx.x, tid = threadIdx.x, lane = tid & 31, w = tid >> 5;
    const float* fp = ftrain + p * TILE;
    for (int i = tid; i < TILE; i += 256) xs[i] = fp[i];
    __syncthreads();
    for (int s = w; s < SS; s += 8) {
        float acc = 0.f;
        #pragma unroll
        for (int k = 0; k < 20; k++) { float v = xs[(lane + 32 * k) * SS + s]; acc += v * v; }
        acc = warp_sum(acc);
        if (lane == 0) inv_s[s] = 1.f / fmaxf(sqrtf(acc), 1e-12f);
    }
    __syncthreads();
    for (int i = tid; i < TILE; i += 256) g_Ag[p * TILE + i] = xs[i] * inv_s[i % SS];
    for (int c = tid; c < CC; c += 256) {
        float acc = 0.f; int base = c * SS;
        #pragma unroll
        for (int j = 0; j < SS; j++) acc += xs[base + j] * inv_s[j];
        g_Abar[p * CC + c] = acc * (1.f / 25.f);
    }
}

// ---------------- K2: ftest inverse norms + Bbar ----------------
__global__ void __launch_bounds__(256) cam_prep_test(const float* __restrict__ ftest) {
    extern __shared__ float sm[];
    float* xs    = sm;
    float* inv_s = sm + 16000;
    int q = blockIdx.x, tid = threadIdx.x, lane = tid & 31, w = tid >> 5;
    const float* fq = ftest + q * TILE;
    for (int i = tid; i < TILE; i += 256) xs[i] = fq[i];
    __syncthreads();
    for (int s = w; s < SS; s += 8) {
        float acc = 0.f;
        #pragma unroll
        for (int k = 0; k < 20; k++) { float v = xs[(lane + 32 * k) * SS + s]; acc += v * v; }
        acc = warp_sum(acc);
        if (lane == 0) {
            float iv = 1.f / fmaxf(sqrtf(acc), 1e-12f);
            inv_s[s] = iv;
            g_ntinv[q * SS + s] = iv;
        }
    }
    __syncthreads();
    for (int c = tid; c < CC; c += 256) {
        float acc = 0.f; int base = c * SS;
        #pragma unroll
        for (int j = 0; j < SS; j++) acc += xs[base + j] * inv_s[j];
        g_Bbar[q * CC + c] = acc * (1.f / 25.f);
    }
}

// ---------------- K3: main fused kernel, one CTA per q ----------------
__global__ void __launch_bounds__(256) cam_main(
    const float* __restrict__ ftest,
    const float* __restrict__ conv1_w, const float* __restrict__ conv1_b,
    const float* __restrict__ bn_gamma, const float* __restrict__ bn_beta,
    const float* __restrict__ bn_mean, const float* __restrict__ bn_var,
    const float* __restrict__ conv2_w, const float* __restrict__ conv2_b,
    float* __restrict__ out)
{
    extern __shared__ float sm[];
    float* Bs     = sm + O_BS;
    float* As     = sm + O_AS;
    float* Bbar_s = sm + O_BBAR;
    float* Abar_s = sm + O_ABAR;
    float* u_s    = sm + O_U;
    float* v_s    = sm + O_V;
    float* g1_s   = sm + O_G1;
    float* g2_s   = sm + O_G2;
    float* k1_s   = sm + O_K1;
    float* k2_s   = sm + O_K2;
    float* att_s  = sm + O_ATT;
    float* am_acc = sm + O_AM;
    float* h1a    = sm + O_H1A;
    float* h1b    = sm + O_H1B;
    float* cls_acc= sm + O_CLS;
    float* sc_s   = sm + O_SC;
    float* b1f    = sm + O_B1F;
    float* w1f    = sm + O_W1F;
    float* w2s    = sm + O_W2;
    float* b2s    = sm + O_B2;

    const int q = blockIdx.x;
    const int tid = threadIdx.x, lane = tid & 31, w = tid >> 5;

    // fold BN into conv1 weights
    if (tid < 5) {
        float scv = bn_gamma[tid] * rsqrtf(bn_var[tid] + 1e-5f);
        sc_s[tid] = scv;
        b1f[tid] = (conv1_b[tid] - bn_mean[tid]) * scv + bn_beta[tid];
    }
    if (tid < SS) { b2s[tid] = conv2_b[tid]; am_acc[tid] = 0.f; }
    if (tid >= 32 && tid < 37) cls_acc[tid - 32] = 0.f;
    __syncthreads();
    for (int i = tid; i < 125; i += 256) {
        w1f[i] = conv1_w[i] * sc_s[i / 25];
        w2s[i] = conv2_w[i];
    }
    for (int i = tid; i < CC; i += 256) Bbar_s[i] = g_Bbar[q * CC + i];
    const float* fq = ftest + q * TILE;
    {
        const float* ninv = g_ntinv + q * SS;
        for (int i = tid; i < TILE; i += 256) Bs[i] = fq[i] * ninv[i % SS];
    }
    __syncthreads();

    float bb[20];
    #pragma unroll
    for (int k = 0; k < 20; k++) bb[k] = Bbar_s[lane + 32 * k];

    for (int p = 0; p < PP; ++p) {
        for (int i = tid; i < TILE; i += 256) As[i] = g_Ag[p * TILE + i];
        for (int i = tid; i < CC; i += 256) Abar_s[i] = g_Abar[p * CC + i];
        __syncthreads();

        float ab[20];
        #pragma unroll
        for (int k = 0; k < 20; k++) ab[k] = Abar_s[lane + 32 * k];

        // g1[hw] = A(:,hw) . Bbar ; g2[xy] = B(:,xy) . Abar
        for (int s = w; s < SS; s += 8) {
            float a1 = 0.f, a2 = 0.f;
            int base = lane * SS + s;
            #pragma unroll
            for (int k = 0; k < 20; k++) {
                a1 += As[base + 800 * k] * bb[k];
                a2 += Bs[base + 800 * k] * ab[k];
            }
            a1 = warp_sum(a1); a2 = warp_sum(a2);
            if (lane == 0) { g1_s[s] = a1; g2_s[s] = a2; }
        }
        __syncthreads();

        // kernel net: 25 -> 5 (BN folded, relu) -> 25 (relu)
        if (tid < 10) {
            int i = tid % 5;
            const float* g = (tid < 5) ? g1_s : g2_s;
            float acc = b1f[i];
            #pragma unroll
            for (int j = 0; j < SS; j++) acc += g[j] * w1f[i * 25 + j];
            ((tid < 5) ? h1a : h1b)[i] = fmaxf(acc, 0.f);
        }
        __syncthreads();
        if (tid < 50) {
            int l = tid % 25;
            const float* h = (tid < 25) ? h1a : h1b;
            float acc = b2s[l];
            #pragma unroll
            for (int i2 = 0; i2 < 5; i2++) acc += h[i2] * w2s[l * 5 + i2];
            ((tid < 25) ? k1_s : k2_s)[l] = fmaxf(acc, 0.f);
        }
        __syncthreads();

        // u[c] = k1 . A(c,:) ; v[c] = k2 . B(c,:)
        {
            float k1r[25], k2r[25];
            #pragma unroll
            for (int j = 0; j < SS; j++) { k1r[j] = k1_s[j]; k2r[j] = k2_s[j]; }
            for (int c = tid; c < CC; c += 256) {
                int base = c * SS;
                float su = 0.f, sv = 0.f;
                #pragma unroll
                for (int j = 0; j < SS; j++) {
                    su += k1r[j] * As[base + j];
                    sv += k2r[j] * Bs[base + j];
                }
                u_s[c] = su; v_s[c] = sv;
            }
        }
        __syncthreads();

        float uu[20], vv[20];
        #pragma unroll
        for (int k = 0; k < 20; k++) { uu[k] = u_s[lane + 32 * k]; vv[k] = v_s[lane + 32 * k]; }

        // att1[xy] = u . B(:,xy) (spill) ; att_t[hw] = A(:,hw) . v
        for (int s = w; s < SS; s += 8) {
            float a1 = 0.f, at = 0.f;
            int base = lane * SS + s;
            #pragma unroll
            for (int k = 0; k < 20; k++) {
                a1 += uu[k] * Bs[base + 800 * k];
                at += As[base + 800 * k] * vv[k];
            }
            a1 = warp_sum(a1); at = warp_sum(at);
            if (lane == 0) {
                g_att1[(p * QQ + q) * SS + s] = a1;
                att_s[s] = at;
            }
        }
        __syncthreads();
        if (tid < SS) am_acc[tid] += att_s[tid];
        if (tid == 0) {
            float ssum = 0.f;
            #pragma unroll
            for (int j = 0; j < SS; j++) ssum += att_s[j];
            cls_acc[p / 5] += ssum;
        }
        __syncthreads();
    }

    // epilogue: softmaxes + outputs for this q
    if (tid == 0) {
        float m = -1e30f;
        for (int j = 0; j < SS; j++) {
            float v2 = am_acc[j] * (1.f / 25.f);
            am_acc[j] = v2; if (v2 > m) m = v2;
        }
        float ssum = 0.f;
        for (int j = 0; j < SS; j++) { float e = expf(am_acc[j] - m); am_acc[j] = e; ssum += e; }
        float inv = 1.f / ssum;
        for (int j = 0; j < SS; j++) am_acc[j] *= inv;

        float cv[5]; float cm = -1e30f;
        for (int i = 0; i < 5; i++) { cv[i] = cls_acc[i] * (1.f / 125.f); if (cv[i] > cm) cm = cv[i]; }
        float cs2 = 0.f;
        for (int i = 0; i < 5; i++) { cv[i] = expf(cv[i] - cm); cs2 += cv[i]; }
        float ci = 1.f / cs2;
        for (int i = 0; i < 5; i++) out[OFT_CLS + q * 5 + i] = cv[i] * ci;
    }
    __syncthreads();
    if (tid < SS) out[OFT_AM + q * SS + tid] = am_acc[tid];
    for (int i = tid; i < TILE; i += 256)
        out[OFT_TE + q * TILE + i] = fq[i] * (am_acc[i % SS] + 1.f);
}

// ---------------- K4: reduce att1 over q, softmax, ftrain_out ----------------
__global__ void __launch_bounds__(256) cam_final_train(const float* __restrict__ ftrain,
                                                       float* __restrict__ out) {
    __shared__ float part[256];
    __shared__ float att_s[SS];
    int p = blockIdx.x, tid = threadIdx.x;
    float acc = 0.f;
    if (tid < 250) {
        int xy = tid % 25, ch = tid / 25;
        const float* base = g_att1 + (size_t)p * QQ * SS + xy;
        for (int qq = ch; qq < QQ; qq += 10) acc += base[qq * SS];
    }
    part[tid] = acc;
    __syncthreads();
    if (tid < SS) {
        float s2 = 0.f;
        #pragma unroll
        for (int ch = 0; ch < 10; ch++) s2 += part[ch * 25 + tid];
        att_s[tid] = s2 * (1.f / (float)QQ);
    }
    __syncthreads();
    if (tid == 0) {
        float m = -1e30f;
        for (int j = 0; j < SS; j++) if (att_s[j] > m) m = att_s[j];
        float ssum = 0.f;
        for (int j = 0; j < SS; j++) { float e = expf(att_s[j] - m); att_s[j] = e; ssum += e; }
        float inv = 1.f / ssum;
        for (int j = 0; j < SS; j++) att_s[j] *= inv;
    }
    __syncthreads();
    const float* fp = ftrain + p * TILE;
    for (int i = tid; i < TILE; i += 256)
        out[p * TILE + i] = fp[i] * (att_s[i % SS] + 1.f);
}

// ---------------- launch ----------------
extern "C" void kernel_launch(void* const* d_in, const int* in_sizes, int n_in,
                              void* d_out, int out_size) {
    const float* ftrain  = (const float*)d_in[0];
    const float* ftest   = (const float*)d_in[1];
    const float* conv1_w = (const float*)d_in[6];
    const float* conv1_b = (const float*)d_in[7];
    const float* bn_gamma= (const float*)d_in[8];
    const float* bn_beta = (const float*)d_in[9];
    const float* bn_mean = (const float*)d_in[10];
    const float* bn_var  = (const float*)d_in[11];
    const float* conv2_w = (const float*)d_in[12];
    const float* conv2_b = (const float*)d_in[13];
    float* out = (float*)d_out;

    const int prep_smem = (16000 + 32) * 4;
    cudaFuncSetAttribute(cam_prep_train, cudaFuncAttributeMaxDynamicSharedMemorySize, prep_smem);
    cudaFuncSetAttribute(cam_prep_test,  cudaFuncAttributeMaxDynamicSharedMemorySize, prep_smem);
    cudaFuncSetAttribute(cam_main,       cudaFuncAttributeMaxDynamicSharedMemorySize, SM_BYTES);

    cam_prep_train<<<PP, 256, prep_smem>>>(ftrain);
    cam_prep_test<<<QQ, 256, prep_smem>>>(ftest);
    cam_main<<<QQ, 256, SM_BYTES>>>(ftest, conv1_w, conv1_b, bn_gamma, bn_beta,
                                    bn_mean, bn_var, conv2_w, conv2_b, out);
    cam_final_train<<<PP, 256>>>(ftrain, out);
}

// round 2
// speedup vs baseline: 1.5902x; 1.5902x over previous
#include <cuda_runtime.h>
#include <math.h>
#include <stdint.h>

// ---------------- problem constants ----------------
#define PP   25
#define QQ   2000
#define CC   640
#define SS   25
#define TILE 16000

// output layout: [ftrain_out 400000][ftest_out 32000000][am 50000][cls 10000]
#define OFT_TE  400000
#define OFT_AM  32400000
#define OFT_CLS 32450000

// ---------------- device scratch ----------------
__device__ float g_Ag[PP * TILE];        // normalized ftrain [p][c][hw]
__device__ float g_Abar[PP * CC];        // mean over hw of normalized ftrain
__device__ float g_att1[PP * QQ * SS];   // att1[p][q][xy] spill

// ---------------- smem layout (floats) ----------------
#define O_BS    0
#define O_AS0   16000
#define O_AS1   32000
#define O_BBAR  48000
#define O_ABAR  48640
#define O_U     49280
#define O_V     49920
#define O_G1    50560
#define O_G2    50585
#define O_K1    50610
#define O_K2    50635
#define O_AM5   50660   /* 5 x 25 */
#define O_H1A   50785
#define O_H1B   50790
#define O_B1F   50795
#define O_W1F   50800   /* 125 */
#define O_W2    50925   /* 125 */
#define O_B2    51050   /* 25 */
#define O_NINV  51075
#define O_NT    51100
#define O_T     51125
#define SM_FLOATS 51152
#define SM_BYTES (SM_FLOATS * 4)

__device__ __forceinline__ float warp_sum(float v) {
    #pragma unroll
    for (int o = 16; o; o >>= 1) v += __shfl_xor_sync(0xffffffffu, v, o);
    return v;
}

__device__ __forceinline__ void cp_async16(uint32_t smem_addr, const void* gptr) {
    asm volatile("cp.async.cg.shared.global [%0], [%1], 16;" :: "r"(smem_addr), "l"(gptr));
}
#define CP_COMMIT() asm volatile("cp.async.commit_group;")
#define CP_WAIT0()  asm volatile("cp.async.wait_group 0;" ::: "memory")

// ---------------- K1: normalize ftrain, store A + Abar ----------------
__global__ void __launch_bounds__(256) cam_prep_train(const float* __restrict__ ftrain) {
    extern __shared__ float sm[];
    float* xs    = sm;          // 16000
    float* inv_s = sm + 16000;  // 25
    int p = blockIdx.x, tid = threadIdx.x, lane = tid & 31, w = tid >> 5;
    const float4* fp4 = (const float4*)(ftrain + p * TILE);
    float4* xs4 = (float4*)xs;
    for (int i = tid; i < 4000; i += 256) xs4[i] = fp4[i];
    __syncthreads();
    for (int s = w; s < SS; s += 8) {
        float acc = 0.f;
        #pragma unroll
        for (int k = 0; k < 20; k++) { float v = xs[(lane + 32 * k) * SS + s]; acc += v * v; }
        acc = warp_sum(acc);
        if (lane == 0) inv_s[s] = 1.f / fmaxf(sqrtf(acc), 1e-12f);
    }
    __syncthreads();
    for (int i = tid; i < TILE; i += 256) g_Ag[p * TILE + i] = xs[i] * inv_s[i % SS];
    for (int c = tid; c < CC; c += 256) {
        float acc = 0.f; int base = c * SS;
        #pragma unroll
        for (int j = 0; j < SS; j++) acc += xs[base + j] * inv_s[j];
        g_Abar[p * CC + c] = acc * (1.f / 25.f);
    }
}

// ---------------- K2: main fused kernel, one CTA per q ----------------
__global__ void __launch_bounds__(512, 1) cam_main(
    const float* __restrict__ ftest,
    const float* __restrict__ conv1_w, const float* __restrict__ conv1_b,
    const float* __restrict__ bn_gamma, const float* __restrict__ bn_beta,
    const float* __restrict__ bn_mean, const float* __restrict__ bn_var,
    const float* __restrict__ conv2_w, const float* __restrict__ conv2_b,
    float* __restrict__ out)
{
    extern __shared__ float sm[];
    const int tid = threadIdx.x, lane = tid & 31, w = tid >> 5;
    const int q = blockIdx.x;
    uint32_t smb = (uint32_t)__cvta_generic_to_shared(sm);

    // prefetch As for p=0 into buffer 0
    {
        const float* src = g_Ag;
        for (int i = tid; i < 4000; i += 512)
            cp_async16(smb + (uint32_t)(O_AS0 + i * 4) * 4u, src + i * 4);
        CP_COMMIT();
    }

    // fold BN into conv1; stage small weights
    for (int i = tid; i < 125; i += 512) {
        int cc = i / 25;
        sm[O_W1F + i] = conv1_w[i] * bn_gamma[cc] * rsqrtf(bn_var[cc] + 1e-5f);
        sm[O_W2 + i]  = conv2_w[i];
    }
    if (tid < 5) {
        float scv = bn_gamma[tid] * rsqrtf(bn_var[tid] + 1e-5f);
        sm[O_B1F + tid] = (conv1_b[tid] - bn_mean[tid]) * scv + bn_beta[tid];
    }
    if (tid < SS) sm[O_B2 + tid] = conv2_b[tid];
    for (int i = tid; i < 125; i += 512) sm[O_AM5 + i] = 0.f;

    // load raw ftest tile
    const float4* fq4 = (const float4*)(ftest + q * TILE);
    float4* Bs4 = (float4*)(sm + O_BS);
    for (int i = tid; i < 4000; i += 512) Bs4[i] = fq4[i];
    __syncthreads();

    // per-spatial norms
    for (int s = w; s < SS; s += 16) {
        float acc = 0.f;
        #pragma unroll
        for (int k = 0; k < 20; k++) { float v = sm[O_BS + (lane + 32 * k) * SS + s]; acc += v * v; }
        acc = warp_sum(acc);
        if (lane == 0) {
            float n = sqrtf(acc);
            sm[O_NT + s] = n;
            sm[O_NINV + s] = 1.f / fmaxf(n, 1e-12f);
        }
    }
    __syncthreads();
    // normalize in place
    for (int i = tid; i < TILE; i += 512) sm[O_BS + i] *= sm[O_NINV + i % SS];
    __syncthreads();
    // Bbar
    for (int c = tid; c < CC; c += 512) {
        float acc = 0.f; int base = O_BS + c * SS;
        #pragma unroll
        for (int j = 0; j < SS; j++) acc += sm[base + j];
        sm[O_BBAR + c] = acc * (1.f / 25.f);
    }
    // (B1 at loop top covers Bbar visibility)

    for (int p = 0; p < PP; ++p) {
        // stage Abar for this p (tiny, L2-resident)
        for (int c = tid; c < CC; c += 512) sm[O_ABAR + c] = g_Abar[p * CC + c];
        CP_WAIT0();
        __syncthreads();                         // B1: As[cur] + Abar + (p==0: Bbar) ready
        const float* A = sm + ((p & 1) ? O_AS1 : O_AS0);
        if (p + 1 < PP) {
            uint32_t dst = smb + (uint32_t)(((p & 1) ? O_AS0 : O_AS1)) * 4u;
            const float* src = g_Ag + (p + 1) * TILE;
            for (int i = tid; i < 4000; i += 512)
                cp_async16(dst + (uint32_t)(i * 16), src + i * 4);
            CP_COMMIT();
        }

        // g1[s] = A(:,s).Bbar ; g2[s] = B(:,s).Abar
        for (int s = w; s < SS; s += 16) {
            float a1 = 0.f, a2 = 0.f;
            #pragma unroll
            for (int k = 0; k < 20; k++) {
                int c = lane + 32 * k;
                a1 += A[c * SS + s] * sm[O_BBAR + c];
                a2 += sm[O_BS + c * SS + s] * sm[O_ABAR + c];
            }
            a1 = warp_sum(a1); a2 = warp_sum(a2);
            if (lane == 0) { sm[O_G1 + s] = a1; sm[O_G2 + s] = a2; }
        }
        __syncthreads();                         // B2

        // kernel net: single warp, fused 25->5->25 twice
        if (w == 0) {
            if (lane < 5) {
                float acc = sm[O_B1F + lane];
                #pragma unroll
                for (int j = 0; j < SS; j++) acc += sm[O_G1 + j] * sm[O_W1F + lane * 25 + j];
                sm[O_H1A + lane] = fmaxf(acc, 0.f);
            } else if (lane >= 8 && lane < 13) {
                int i = lane - 8;
                float acc = sm[O_B1F + i];
                #pragma unroll
                for (int j = 0; j < SS; j++) acc += sm[O_G2 + j] * sm[O_W1F + i * 25 + j];
                sm[O_H1B + i] = fmaxf(acc, 0.f);
            }
            __syncwarp();
            if (lane < 25) {
                float a1 = sm[O_B2 + lane], a2 = a1;
                #pragma unroll
                for (int i = 0; i < 5; i++) {
                    float wv = sm[O_W2 + lane * 5 + i];
                    a1 += sm[O_H1A + i] * wv;
                    a2 += sm[O_H1B + i] * wv;
                }
                sm[O_K1 + lane] = fmaxf(a1, 0.f);
                sm[O_K2 + lane] = fmaxf(a2, 0.f);
            }
        }
        __syncthreads();                         // B3

        // u[c] = k1 . A(c,:) ; v[c] = k2 . B(c,:)
        for (int c = tid; c < CC; c += 512) {
            float su = 0.f, sv = 0.f;
            int ba = c * SS;
            #pragma unroll
            for (int j = 0; j < SS; j++) {
                float k1v = sm[O_K1 + j], k2v = sm[O_K2 + j];
                su += k1v * A[ba + j];
                sv += k2v * sm[O_BS + ba + j];
            }
            sm[O_U + c] = su; sm[O_V + c] = sv;
        }
        __syncthreads();                         // B4

        // att1[s] = u . B(:,s) (spill) ; att_t[s] = A(:,s) . v (accumulate)
        float* attq = g_att1 + (size_t)(p * QQ + q) * SS;
        const int grp = p / 5;
        for (int s = w; s < SS; s += 16) {
            float a1 = 0.f, at = 0.f;
            #pragma unroll
            for (int k = 0; k < 20; k++) {
                int c = lane + 32 * k;
                a1 += sm[O_U + c] * sm[O_BS + c * SS + s];
                at += A[c * SS + s] * sm[O_V + c];
            }
            a1 = warp_sum(a1); at = warp_sum(at);
            if (lane == 0) {
                attq[s] = a1;
                sm[O_AM5 + grp * SS + s] += at;   // owner-exclusive slot: no race
            }
        }
        // next iteration's B1 orders everything
    }
    __syncthreads();

    // epilogue: am softmax, cls softmax, outputs
    if (tid == 0) {
        float am[25]; float m = -1e30f;
        for (int s = 0; s < 25; s++) {
            float v = 0.f;
            #pragma unroll
            for (int g = 0; g < 5; g++) v += sm[O_AM5 + g * 25 + s];
            v *= (1.f / 25.f);
            am[s] = v; if (v > m) m = v;
        }
        float ssum = 0.f;
        for (int s = 0; s < 25; s++) { float e = expf(am[s] - m); am[s] = e; ssum += e; }
        float inv = 1.f / ssum;
        for (int s = 0; s < 25; s++) {
            float a = am[s] * inv;
            out[OFT_AM + q * SS + s] = a;
            sm[O_T + s] = sm[O_NT + s] * (a + 1.f);  // reconstruct raw ftest * (am+1)
        }
        float cv[5]; float cm = -1e30f;
        for (int g = 0; g < 5; g++) {
            float v = 0.f;
            for (int s = 0; s < 25; s++) v += sm[O_AM5 + g * 25 + s];
            v *= (1.f / 125.f);
            cv[g] = v; if (v > cm) cm = v;
        }
        float cs = 0.f;
        for (int g = 0; g < 5; g++) { cv[g] = expf(cv[g] - cm); cs += cv[g]; }
        float ci = 1.f / cs;
        for (int g = 0; g < 5; g++) out[OFT_CLS + q * 5 + g] = cv[g] * ci;
    }
    __syncthreads();

    float4* outq = (float4*)(out + OFT_TE + (size_t)q * TILE);
    for (int i = tid; i < 4000; i += 512) {
        float4 b = Bs4[i];
        int s = (i * 4) % 25;
        float4 o;
        o.x = b.x * sm[O_T + s]; s = (s == 24) ? 0 : s + 1;
        o.y = b.y * sm[O_T + s]; s = (s == 24) ? 0 : s + 1;
        o.z = b.z * sm[O_T + s]; s = (s == 24) ? 0 : s + 1;
        o.w = b.w * sm[O_T + s];
        outq[i] = o;
    }
}

// ---------------- K3: reduce att1 over q, softmax, ftrain_out ----------------
__global__ void __launch_bounds__(256) cam_final_train(const float* __restrict__ ftrain,
                                                       float* __restrict__ out) {
    __shared__ float part[256];
    __shared__ float att_s[SS];
    int p = blockIdx.x, tid = threadIdx.x;
    float acc = 0.f;
    if (tid < 250) {
        int xy = tid % 25, ch = tid / 25;
        const float* base = g_att1 + (size_t)p * QQ * SS + xy;
        for (int qq = ch; qq < QQ; qq += 10) acc += base[qq * SS];
    }
    part[tid] = acc;
    __syncthreads();
    if (tid < SS) {
        float s2 = 0.f;
        #pragma unroll
        for (int ch = 0; ch < 10; ch++) s2 += part[ch * 25 + tid];
        att_s[tid] = s2 * (1.f / (float)QQ);
    }
    __syncthreads();
    if (tid == 0) {
        float m = -1e30f;
        for (int j = 0; j < SS; j++) if (att_s[j] > m) m = att_s[j];
        float ssum = 0.f;
        for (int j = 0; j < SS; j++) { float e = expf(att_s[j] - m); att_s[j] = e; ssum += e; }
        float inv = 1.f / ssum;
        for (int j = 0; j < SS; j++) att_s[j] *= inv;
    }
    __syncthreads();
    const float* fp = ftrain + p * TILE;
    for (int i = tid; i < TILE; i += 256)
        out[p * TILE + i] = fp[i] * (att_s[i % SS] + 1.f);
}

// ---------------- launch ----------------
extern "C" void kernel_launch(void* const* d_in, const int* in_sizes, int n_in,
                              void* d_out, int out_size) {
    const float* ftrain  = (const float*)d_in[0];
    const float* ftest   = (const float*)d_in[1];
    const float* conv1_w = (const float*)d_in[6];
    const float* conv1_b = (const float*)d_in[7];
    const float* bn_gamma= (const float*)d_in[8];
    const float* bn_beta = (const float*)d_in[9];
    const float* bn_mean = (const float*)d_in[10];
    const float* bn_var  = (const float*)d_in[11];
    const float* conv2_w = (const float*)d_in[12];
    const float* conv2_b = (const float*)d_in[13];
    float* out = (float*)d_out;

    const int prep_smem = (16000 + 32) * 4;
    cudaFuncSetAttribute(cam_prep_train, cudaFuncAttributeMaxDynamicSharedMemorySize, prep_smem);
    cudaFuncSetAttribute(cam_main,       cudaFuncAttributeMaxDynamicSharedMemorySize, SM_BYTES);

    cam_prep_train<<<PP, 256, prep_smem>>>(ftrain);
    cam_main<<<QQ, 512, SM_BYTES>>>(ftest, conv1_w, conv1_b, bn_gamma, bn_beta,
                                    bn_mean, bn_var, conv2_w, conv2_b, out);
    cam_final_train<<<PP, 256>>>(ftrain, out);
}

// round 4
// speedup vs baseline: 5.3130x; 3.3411x over previous
#include <cuda_runtime.h>
#include <cuda_fp16.h>
#include <math.h>
#include <stdint.h>

// ---------------- problem constants ----------------
#define PP   25
#define QQ   2000
#define CC   640
#define SS   25
#define TILE 16000          // CC*SS

#define MPAD 640            // Gram rows padded (625 valid)
#define NKC  40             // K chunks of 16
#define CHUNK_BYTES (MPAD * 32)   // 640 rows x 16 halves = 20480 B
#define NRING 4

// output layout: [ftrain_out 400000][ftest_out 32000000][am 50000][cls 10000]
#define OFT_TE  400000
#define OFT_AM  32400000
#define OFT_CLS 32450000

// ---------------- device scratch ----------------
__device__ __align__(16) unsigned char g_Ah[NKC * CHUNK_BYTES]; // swizzled fp16 A image
__device__ float g_att1[PP * QQ * SS];                          // att1[p][q][xy]

// ---------------- smem byte offsets (main kernel) ----------------
#define OB_A     0                       // ring: 4 x 20480
#define OB_B     81920                   // 32 rows x 648 halves = 41472
#define OB_G     123392                  // 625*25 fp32 = 62500 (also fq staging 64000)
#define OB_KNET  185892                  // 25 x 112 fp32 = 11200
#define OB_ATTT  197092                  // 25 x 25 fp32 = 2500
#define OB_W1F   199592                  // 125 f
#define OB_W2    200092                  // 125 f
#define OB_B1F   200592                  // 5 f
#define OB_B2S   200612                  // 25 f
#define OB_NINV  200712                  // 25 f
#define OB_TS    200812                  // 25 f
#define SMEM_BYTES 200960

#define GI   (OB_G/4)
#define KNI  (OB_KNET/4)
#define ATI  (OB_ATTT/4)

__device__ __forceinline__ float warp_sum(float v) {
    #pragma unroll
    for (int o = 16; o; o >>= 1) v += __shfl_xor_sync(0xffffffffu, v, o);
    return v;
}
__device__ __forceinline__ void cp_async16(uint32_t smem_addr, const void* gptr) {
    asm volatile("cp.async.cg.shared.global [%0], [%1], 16;" :: "r"(smem_addr), "l"(gptr));
}
#define CP_COMMIT() asm volatile("cp.async.commit_group;")
#define CP_WAIT2()  asm volatile("cp.async.wait_group 2;" ::: "memory")
#define CP_WAIT0()  asm volatile("cp.async.wait_group 0;" ::: "memory")

__device__ __forceinline__ void ldsm_x4(uint32_t& r0, uint32_t& r1, uint32_t& r2, uint32_t& r3,
                                        uint32_t addr) {
    asm volatile("ldmatrix.sync.aligned.m8n8.x4.shared.b16 {%0,%1,%2,%3}, [%4];"
                 : "=r"(r0), "=r"(r1), "=r"(r2), "=r"(r3) : "r"(addr));
}
__device__ __forceinline__ void mma16816(float& d0, float& d1, float& d2, float& d3,
                                         uint32_t a0, uint32_t a1, uint32_t a2, uint32_t a3,
                                         uint32_t b0, uint32_t b1) {
    asm volatile("mma.sync.aligned.m16n8k16.row.col.f32.f16.f16.f32 "
                 "{%0,%1,%2,%3}, {%4,%5,%6,%7}, {%8,%9}, {%0,%1,%2,%3};"
                 : "+f"(d0), "+f"(d1), "+f"(d2), "+f"(d3)
                 : "r"(a0), "r"(a1), "r"(a2), "r"(a3), "r"(b0), "r"(b1));
}

// ---------------- K1: build swizzled fp16 A image ----------------
// layout: chunk kc (k=16 wide), row m (0..639), 32 bytes per row.
// within row: half k at byte ((k>>3) ^ ((m>>2)&1))*16 + (k&7)*2  (ldmatrix-conflict-free)
__global__ void __launch_bounds__(256) cam_prep_A(const float* __restrict__ ftrain) {
    extern __shared__ float sm[];
    float* xs    = sm;          // 16000
    float* inv_s = sm + 16000;  // 25
    int p = blockIdx.x, tid = threadIdx.x, lane = tid & 31, w = tid >> 5;
    const float4* fp4 = (const float4*)(ftrain + p * TILE);
    float4* xs4 = (float4*)xs;
    for (int i = tid; i < 4000; i += 256) xs4[i] = fp4[i];
    __syncthreads();
    for (int s = w; s < SS; s += 8) {
        float acc = 0.f;
        #pragma unroll
        for (int k = 0; k < 20; k++) { float v = xs[(lane + 32 * k) * SS + s]; acc += v * v; }
        acc = warp_sum(acc);
        if (lane == 0) inv_s[s] = 1.f / fmaxf(sqrtf(acc), 1e-12f);
    }
    __syncthreads();
    for (int idx = tid; idx < TILE; idx += 256) {
        int c = idx / SS, s = idx - c * SS;
        __half v = __float2half_rn(xs[idx] * inv_s[s]);
        int m = p * SS + s;            // Gram row (0..624)
        int kc = c >> 4, k = c & 15;
        uint32_t off = (uint32_t)((((k >> 3) ^ ((m >> 2) & 1)) << 4) + ((k & 7) << 1));
        *(__half*)(g_Ah + (size_t)(kc * MPAD + m) * 32 + off) = v;
    }
}

// ---------------- K2: main per-q kernel (HMMA Gram + fused epilogue) ----------------
__global__ void __launch_bounds__(512, 1) cam_main(
    const float* __restrict__ ftest,
    const float* __restrict__ conv1_w, const float* __restrict__ conv1_b,
    const float* __restrict__ bn_gamma, const float* __restrict__ bn_beta,
    const float* __restrict__ bn_mean, const float* __restrict__ bn_var,
    const float* __restrict__ conv2_w, const float* __restrict__ conv2_b,
    float* __restrict__ out)
{
    extern __shared__ char smraw[];
    float* smf = (float*)smraw;
    const int tid = threadIdx.x, lane = tid & 31, w = tid >> 5;
    const int q = blockIdx.x;
    const uint32_t smb = (uint32_t)__cvta_generic_to_shared(smraw);

    // start streaming A chunks 0..2 immediately (ring depth 3 in flight)
    #pragma unroll
    for (int pc = 0; pc < 3; pc++) {
        for (int j = tid; j < CHUNK_BYTES / 16; j += 512)
            cp_async16(smb + OB_A + pc * CHUNK_BYTES + j * 16,
                       g_Ah + (size_t)pc * CHUNK_BYTES + j * 16);
        CP_COMMIT();
    }

    // stage raw fq into G region (temp), load small weights
    const float4* fq4 = (const float4*)(ftest + q * TILE);
    {
        float4* st4 = (float4*)(smraw + OB_G);
        for (int i = tid; i < 4000; i += 512) st4[i] = fq4[i];
    }
    for (int i = tid; i < 125; i += 512) {
        int cc = i / 25;
        smf[OB_W1F/4 + i] = conv1_w[i] * bn_gamma[cc] * rsqrtf(bn_var[cc] + 1e-5f);
        smf[OB_W2/4 + i]  = conv2_w[i];
    }
    if (tid < 5) {
        float scv = bn_gamma[tid] * rsqrtf(bn_var[tid] + 1e-5f);
        smf[OB_B1F/4 + tid] = (conv1_b[tid] - bn_mean[tid]) * scv + bn_beta[tid];
    }
    if (tid < 25) smf[OB_B2S/4 + tid] = conv2_b[tid];
    __syncthreads();

    // per-spatial inverse norms
    const float* fqs = (const float*)(smraw + OB_G);
    for (int s = w; s < SS; s += 16) {
        float acc = 0.f;
        #pragma unroll
        for (int k = 0; k < 20; k++) { float v = fqs[(lane + 32 * k) * SS + s]; acc += v * v; }
        acc = warp_sum(acc);
        if (lane == 0) smf[OB_NINV/4 + s] = 1.f / fmaxf(sqrtf(acc), 1e-12f);
    }
    __syncthreads();

    // build B operand: [n=s][k=c] fp16, rows padded to 648 halves (conflict-free LDS)
    for (int idx = tid; idx < TILE; idx += 512) {
        int c = idx / SS, s = idx - c * SS;
        __half v = __float2half_rn(fqs[idx] * smf[OB_NINV/4 + s]);
        *(__half*)(smraw + OB_B + (s * 648 + c) * 2) = v;
    }
    // zero pad rows 25..31 (keeps mma inputs finite; cols >=25 of G unused anyway)
    for (int i = tid; i < 7 * 324; i += 512) {
        int n = 25 + i / 324, j = i % 324;
        *(uint32_t*)(smraw + OB_B + (n * 648) * 2 + j * 4) = 0u;
    }
    __syncthreads();

    // ---- GEMM: G[625(pad 640) x 32] = A x B^T, K = 640 ----
    float acc[3][4][4];
    #pragma unroll
    for (int t = 0; t < 3; t++)
        #pragma unroll
        for (int n = 0; n < 4; n++)
            #pragma unroll
            for (int e = 0; e < 4; e++) acc[t][n][e] = 0.f;

    const int nrow = lane >> 2;          // 0..7
    const int kq   = lane & 3;           // 0..3
    for (int i = 0; i < NKC; i++) {
        CP_WAIT2();
        __syncthreads();
        if (i + 3 < NKC) {
            int b = (i + 3) & (NRING - 1);
            for (int j = tid; j < CHUNK_BYTES / 16; j += 512)
                cp_async16(smb + OB_A + b * CHUNK_BYTES + j * 16,
                           g_Ah + (size_t)(i + 3) * CHUNK_BYTES + j * 16);
            CP_COMMIT();
        }
        const uint32_t abase = smb + OB_A + (i & (NRING - 1)) * CHUNK_BYTES;

        // B fragments for this k-chunk
        uint32_t bf[4][2];
        #pragma unroll
        for (int nt = 0; nt < 4; nt++) {
            int n = nt * 8 + nrow;
            uint32_t bidx = OB_B + (uint32_t)(n * 648 + i * 16 + kq * 2) * 2;
            bf[nt][0] = *(const uint32_t*)(smraw + bidx);
            bf[nt][1] = *(const uint32_t*)(smraw + bidx + 16);
        }

        #pragma unroll
        for (int tt = 0; tt < 3; tt++) {
            int mt = w + tt * 16;
            if (tt == 2 && w >= 8) break;
            int m = mt * 16 + (lane & 15);
            uint32_t addr = abase + m * 32 + ((((lane >> 4) ^ (m >> 2)) & 1) << 4);
            uint32_t a0, a1, a2, a3;
            ldsm_x4(a0, a1, a2, a3, addr);
            #pragma unroll
            for (int nt = 0; nt < 4; nt++)
                mma16816(acc[tt][nt][0], acc[tt][nt][1], acc[tt][nt][2], acc[tt][nt][3],
                         a0, a1, a2, a3, bf[nt][0], bf[nt][1]);
        }
    }
    CP_WAIT0();
    __syncthreads();   // staging (OB_G) no longer needed; A ring done

    // ---- write G fragments to smem (625 x 25, rows/cols clipped) ----
    #pragma unroll
    for (int tt = 0; tt < 3; tt++) {
        int mt = w + tt * 16;
        if (tt == 2 && w >= 8) break;
        int r0 = mt * 16 + (lane >> 2);
        int r1 = r0 + 8;
        #pragma unroll
        for (int nt = 0; nt < 4; nt++) {
            int c = nt * 8 + (lane & 3) * 2;
            if (c < 25) {
                if (r0 < 625) smf[GI + r0 * 25 + c] = acc[tt][nt][0];
                if (r1 < 625) smf[GI + r1 * 25 + c] = acc[tt][nt][2];
            }
            if (c + 1 < 25) {
                if (r0 < 625) smf[GI + r0 * 25 + c + 1] = acc[tt][nt][1];
                if (r1 < 625) smf[GI + r1 * 25 + c + 1] = acc[tt][nt][3];
            }
        }
    }
    __syncthreads();

    // ---- per-p epilogue: one warp per p ----
    for (int p = w; p < PP; p += 16) {
        float* kn = smf + KNI + p * 112;
        if (lane < 25) {
            float a1 = 0.f, a2 = 0.f;
            int rowb = (p * 25 + lane) * 25;
            int colb = p * 25 * 25 + lane;
            #pragma unroll
            for (int j = 0; j < 25; j++) {
                a1 += smf[GI + rowb + j];
                a2 += smf[GI + colb + j * 25];
            }
            kn[lane]      = a1 * (1.f / 25.f);
            kn[25 + lane] = a2 * (1.f / 25.f);
        }
        __syncwarp();
        if (lane < 5) {
            float a = smf[OB_B1F/4 + lane];
            #pragma unroll
            for (int j = 0; j < 25; j++) a += kn[j] * smf[OB_W1F/4 + lane * 25 + j];
            kn[50 + lane] = fmaxf(a, 0.f);
        } else if (lane >= 8 && lane < 13) {
            int ii = lane - 8;
            float a = smf[OB_B1F/4 + ii];
            #pragma unroll
            for (int j = 0; j < 25; j++) a += kn[25 + j] * smf[OB_W1F/4 + ii * 25 + j];
            kn[55 + ii] = fmaxf(a, 0.f);
        }
        __syncwarp();
        if (lane < 25) {
            float a1 = smf[OB_B2S/4 + lane], a2 = a1;
            #pragma unroll
            for (int ii = 0; ii < 5; ii++) {
                float wv = smf[OB_W2/4 + lane * 5 + ii];
                a1 += kn[50 + ii] * wv;
                a2 += kn[55 + ii] * wv;
            }
            kn[60 + lane] = fmaxf(a1, 0.f);  // k1
            kn[85 + lane] = fmaxf(a2, 0.f);  // k2
        }
        __syncwarp();
        if (lane < 25) {
            float att1 = 0.f, attt = 0.f;
            int colb = p * 25 * 25 + lane;
            int rowb = (p * 25 + lane) * 25;
            #pragma unroll
            for (int j = 0; j < 25; j++) {
                att1 += kn[60 + j] * smf[GI + colb + j * 25];
                attt += smf[GI + rowb + j] * kn[85 + j];
            }
            g_att1[(size_t)(p * QQ + q) * SS + lane] = att1;
            smf[ATI + p * 25 + lane] = attt;
        }
    }
    __syncthreads();

    // ---- am / cls softmaxes ----
    if (tid == 0) {
        float am[25]; float m = -1e30f;
        for (int s = 0; s < 25; s++) {
            float v = 0.f;
            #pragma unroll
            for (int p = 0; p < 25; p++) v += smf[ATI + p * 25 + s];
            v *= (1.f / 25.f);
            am[s] = v; if (v > m) m = v;
        }
        float ssum = 0.f;
        for (int s = 0; s < 25; s++) { float e = expf(am[s] - m); am[s] = e; ssum += e; }
        float inv = 1.f / ssum;
        for (int s = 0; s < 25; s++) {
            float a = am[s] * inv;
            out[OFT_AM + q * SS + s] = a;
            smf[OB_TS/4 + s] = a + 1.f;
        }
        float cv[5]; float cm = -1e30f;
        for (int g = 0; g < 5; g++) {
            float v = 0.f;
            for (int p = g * 5; p < g * 5 + 5; p++)
                for (int s = 0; s < 25; s++) v += smf[ATI + p * 25 + s];
            v *= (1.f / 125.f);
            cv[g] = v; if (v > cm) cm = v;
        }
        float cs = 0.f;
        for (int g = 0; g < 5; g++) { cv[g] = expf(cv[g] - cm); cs += cv[g]; }
        float ci = 1.f / cs;
        for (int g = 0; g < 5; g++) out[OFT_CLS + q * 5 + g] = cv[g] * ci;
    }
    __syncthreads();

    // ---- ftest_out = raw ftest * (am + 1) ----
    float4* outq = (float4*)(out + OFT_TE + (size_t)q * TILE);
    for (int i = tid; i < 4000; i += 512) {
        float4 b = fq4[i];
        int s = (i * 4) % 25;
        float4 o;
        o.x = b.x * smf[OB_TS/4 + s]; s = (s == 24) ? 0 : s + 1;
        o.y = b.y * smf[OB_TS/4 + s]; s = (s == 24) ? 0 : s + 1;
        o.z = b.z * smf[OB_TS/4 + s]; s = (s == 24) ? 0 : s + 1;
        o.w = b.w * smf[OB_TS/4 + s];
        outq[i] = o;
    }
}

// ---------------- K3: reduce att1 over q, softmax, ftrain_out ----------------
__global__ void __launch_bounds__(256) cam_final_train(const float* __restrict__ ftrain,
                                                       float* __restrict__ out) {
    __shared__ float part[256];
    __shared__ float att_s[SS];
    int p = blockIdx.x, tid = threadIdx.x;
    float acc = 0.f;
    if (tid < 250) {
        int xy = tid % 25, ch = tid / 25;
        const float* base = g_att1 + (size_t)p * QQ * SS + xy;
        for (int qq = ch; qq < QQ; qq += 10) acc += base[qq * SS];
    }
    part[tid] = acc;
    __syncthreads();
    if (tid < SS) {
        float s2 = 0.f;
        #pragma unroll
        for (int ch = 0; ch < 10; ch++) s2 += part[ch * 25 + tid];
        att_s[tid] = s2 * (1.f / (float)QQ);
    }
    __syncthreads();
    if (tid == 0) {
        float m = -1e30f;
        for (int j = 0; j < SS; j++) if (att_s[j] > m) m = att_s[j];
        float ssum = 0.f;
        for (int j = 0; j < SS; j++) { float e = expf(att_s[j] - m); att_s[j] = e; ssum += e; }
        float inv = 1.f / ssum;
        for (int j = 0; j < SS; j++) att_s[j] *= inv;
    }
    __syncthreads();
    const float* fp = ftrain + p * TILE;
    for (int i = tid; i < TILE; i += 256)
        out[p * TILE + i] = fp[i] * (att_s[i % SS] + 1.f);
}

// ---------------- launch ----------------
extern "C" void kernel_launch(void* const* d_in, const int* in_sizes, int n_in,
                              void* d_out, int out_size) {
    const float* ftrain  = (const float*)d_in[0];
    const float* ftest   = (const float*)d_in[1];
    const float* conv1_w = (const float*)d_in[6];
    const float* conv1_b = (const float*)d_in[7];
    const float* bn_gamma= (const float*)d_in[8];
    const float* bn_beta = (const float*)d_in[9];
    const float* bn_mean = (const float*)d_in[10];
    const float* bn_var  = (const float*)d_in[11];
    const float* conv2_w = (const float*)d_in[12];
    const float* conv2_b = (const float*)d_in[13];
    float* out = (float*)d_out;

    const int prep_smem = (16000 + 32) * 4;
    cudaFuncSetAttribute(cam_prep_A, cudaFuncAttributeMaxDynamicSharedMemorySize, prep_smem);
    cudaFuncSetAttribute(cam_main,   cudaFuncAttributeMaxDynamicSharedMemorySize, SMEM_BYTES);

    cam_prep_A<<<PP, 256, prep_smem>>>(ftrain);
    cam_main<<<QQ, 512, SMEM_BYTES>>>(ftest, conv1_w, conv1_b, bn_gamma, bn_beta,
                                      bn_mean, bn_var, conv2_w, conv2_b, out);
    cam_final_train<<<PP, 256>>>(ftrain, out);
}

// round 5
// speedup vs baseline: 7.5814x; 1.4269x over previous
#include <cuda_runtime.h>
#include <cuda_fp16.h>
#include <math.h>
#include <stdint.h>

// ---------------- problem constants ----------------
#define PP   25
#define QQ   2000
#define CC   640
#define SS   25
#define TILE 16000          // CC*SS

#define MPAD 640            // Gram rows padded (625 valid)
#define NKC  40             // K chunks of 16
#define CHUNK_BYTES (MPAD * 32)   // 20480 B
#define NRING 3
#define BQ_BYTES 41472      // 32 rows x 648 halves x 2B

// output layout: [ftrain_out 400000][ftest_out 32000000][am 50000][cls 10000]
#define OFT_TE  400000
#define OFT_AM  32400000
#define OFT_CLS 32450000

// ---------------- device scratch ----------------
__device__ __align__(16) unsigned char g_Ah[NKC * CHUNK_BYTES]; // swizzled fp16 A image
__device__ float g_att1[PP * QQ * SS];                          // att1[p][q][xy]

// ---------------- smem byte offsets (cam_main) ----------------
#define OB_A     0                        // ring: 3 x 20480 = 61440
#define OB_B     61440                    // 2 x 41472 = 82944 -> 144384
#define OB_G     144384                   // G fp32 62500 (staging region 64000)
#define OB_ATT   208384                   // 25x25 fp32 = 2500
#define OB_KN    210884                   // 16 x 112 x 4 = 7168
#define OB_W1F   218052                   // 125 f
#define OB_W2    218552                   // 125 f
#define OB_B1F   219052                   // 5 f
#define OB_B2S   219072                   // 25 f
#define OB_NINV  219172                   // 2 x 25 f
#define OB_TS    219372                   // 25 f
#define SMEM_BYTES 219472

#define GI   (OB_G/4)
#define ATI  (OB_ATT/4)
#define KNI  (OB_KN/4)

__device__ __forceinline__ float warp_sum(float v) {
    #pragma unroll
    for (int o = 16; o; o >>= 1) v += __shfl_xor_sync(0xffffffffu, v, o);
    return v;
}
__device__ __forceinline__ void cp_async16(uint32_t smem_addr, const void* gptr) {
    asm volatile("cp.async.cg.shared.global [%0], [%1], 16;" :: "r"(smem_addr), "l"(gptr));
}
#define CP_COMMIT() asm volatile("cp.async.commit_group;")
#define CP_WAIT1()  asm volatile("cp.async.wait_group 1;" ::: "memory")
#define CP_WAIT0()  asm volatile("cp.async.wait_group 0;" ::: "memory")

__device__ __forceinline__ void ldsm_x4(uint32_t& r0, uint32_t& r1, uint32_t& r2, uint32_t& r3,
                                        uint32_t addr) {
    asm volatile("ldmatrix.sync.aligned.m8n8.x4.shared.b16 {%0,%1,%2,%3}, [%4];"
                 : "=r"(r0), "=r"(r1), "=r"(r2), "=r"(r3) : "r"(addr));
}
__device__ __forceinline__ void mma16816(float& d0, float& d1, float& d2, float& d3,
                                         uint32_t a0, uint32_t a1, uint32_t a2, uint32_t a3,
                                         uint32_t b0, uint32_t b1) {
    asm volatile("mma.sync.aligned.m16n8k16.row.col.f32.f16.f16.f32 "
                 "{%0,%1,%2,%3}, {%4,%5,%6,%7}, {%8,%9}, {%0,%1,%2,%3};"
                 : "+f"(d0), "+f"(d1), "+f"(d2), "+f"(d3)
                 : "r"(a0), "r"(a1), "r"(a2), "r"(a3), "r"(b0), "r"(b1));
}

// ---------------- K1: build swizzled fp16 A image (smem-staged, coalesced out) --------
__global__ void __launch_bounds__(256) cam_prep_A(const float* __restrict__ ftrain) {
    extern __shared__ float sm[];
    float* xs    = sm;                       // 16000 f
    float* inv_s = sm + 16000;               // 25 f
    unsigned char* buf = (unsigned char*)sm + 64128;  // 32000 B (40 chunks x 25 rows x 32B)
    int p = blockIdx.x, tid = threadIdx.x, lane = tid & 31, w = tid >> 5;
    const float4* fp4 = (const float4*)(ftrain + p * TILE);
    float4* xs4 = (float4*)xs;
    for (int i = tid; i < 4000; i += 256) xs4[i] = fp4[i];
    __syncthreads();
    for (int s = w; s < SS; s += 8) {
        float acc = 0.f;
        #pragma unroll
        for (int k = 0; k < 20; k++) { float v = xs[(lane + 32 * k) * SS + s]; acc += v * v; }
        acc = warp_sum(acc);
        if (lane == 0) inv_s[s] = 1.f / fmaxf(sqrtf(acc), 1e-12f);
    }
    __syncthreads();
    for (int idx = tid; idx < TILE; idx += 256) {
        int c = idx / SS, s = idx - c * SS;
        __half v = __float2half_rn(xs[idx] * inv_s[s]);
        int m = p * SS + s;
        int kc = c >> 4, k = c & 15;
        uint32_t off = (uint32_t)((((k >> 3) ^ ((m >> 2) & 1)) << 4) + ((k & 7) << 1));
        *(__half*)(buf + kc * 800 + s * 32 + off) = v;
    }
    __syncthreads();
    // coalesced write: per chunk, 25 rows (800B) at (kc*640 + p*25)*32
    for (int i = tid; i < 2000; i += 256) {
        int kc = i / 50, j = i - kc * 50;
        *(float4*)(g_Ah + (size_t)(kc * MPAD + p * SS) * 32 + j * 16) =
            *(const float4*)(buf + kc * 800 + j * 16);
    }
}

// ---------------- K2: main kernel, 2 q per CTA ----------------
__global__ void __launch_bounds__(512, 1) cam_main(
    const float* __restrict__ ftest,
    const float* __restrict__ conv1_w, const float* __restrict__ conv1_b,
    const float* __restrict__ bn_gamma, const float* __restrict__ bn_beta,
    const float* __restrict__ bn_mean, const float* __restrict__ bn_var,
    const float* __restrict__ conv2_w, const float* __restrict__ conv2_b,
    float* __restrict__ out)
{
    extern __shared__ char smraw[];
    float* smf = (float*)smraw;
    const int tid = threadIdx.x, lane = tid & 31, w = tid >> 5;
    const int h = w >> 3;                 // warp half: q index within CTA
    const int wl = w & 7;                 // warp within half
    const int q0 = blockIdx.x * 2;
    const uint32_t smb = (uint32_t)__cvta_generic_to_shared(smraw);

    // prefetch A chunks 0,1
    #pragma unroll
    for (int pc = 0; pc < 2; pc++) {
        for (int j = tid; j < CHUNK_BYTES / 16; j += 512)
            cp_async16(smb + OB_A + pc * CHUNK_BYTES + j * 16,
                       g_Ah + (size_t)pc * CHUNK_BYTES + j * 16);
        CP_COMMIT();
    }

    // small weights (BN folded into conv1)
    for (int i = tid; i < 125; i += 512) {
        int cc = i / 25;
        smf[OB_W1F/4 + i] = conv1_w[i] * bn_gamma[cc] * rsqrtf(bn_var[cc] + 1e-5f);
        smf[OB_W2/4 + i]  = conv2_w[i];
    }
    if (tid < 5) {
        float scv = bn_gamma[tid] * rsqrtf(bn_var[tid] + 1e-5f);
        smf[OB_B1F/4 + tid] = (conv1_b[tid] - bn_mean[tid]) * scv + bn_beta[tid];
    }
    if (tid < 25) smf[OB_B2S/4 + tid] = conv2_b[tid];

    // ---- stage + normalize + build B for q0, q1 ----
    for (int qi = 0; qi < 2; qi++) {
        const float4* fq4 = (const float4*)(ftest + (size_t)(q0 + qi) * TILE);
        float4* st4 = (float4*)(smraw + OB_G);
        __syncthreads();                       // staging region free
        for (int i = tid; i < 4000; i += 512) st4[i] = fq4[i];
        __syncthreads();
        const float* fqs = (const float*)(smraw + OB_G);
        for (int s = w; s < SS; s += 16) {
            float acc = 0.f;
            #pragma unroll
            for (int k = 0; k < 20; k++) { float v = fqs[(lane + 32 * k) * SS + s]; acc += v * v; }
            acc = warp_sum(acc);
            if (lane == 0) smf[OB_NINV/4 + qi * 25 + s] = 1.f / fmaxf(sqrtf(acc), 1e-12f);
        }
        __syncthreads();
        // B[n=s][k=c], row stride 648 halves
        for (int idx = tid; idx < TILE; idx += 512) {
            int c = idx / SS, s = idx - c * SS;
            __half v = __float2half_rn(fqs[idx] * smf[OB_NINV/4 + qi * 25 + s]);
            *(__half*)(smraw + OB_B + qi * BQ_BYTES + (s * 648 + c) * 2) = v;
        }
        // zero rows 25..31
        for (int i = tid; i < 7 * 324; i += 512) {
            int n = 25 + i / 324, j = i - (n - 25) * 324;
            *(uint32_t*)(smraw + OB_B + qi * BQ_BYTES + n * 1296 + j * 4) = 0u;
        }
    }
    __syncthreads();

    // ---- GEMM: each warp 5 m-tiles x 4 n-tiles for its q ----
    float acc[5][4][4];
    #pragma unroll
    for (int t = 0; t < 5; t++)
        #pragma unroll
        for (int n = 0; n < 4; n++)
            #pragma unroll
            for (int e = 0; e < 4; e++) acc[t][n][e] = 0.f;

    const int nrow = lane >> 2;          // 0..7
    const int kq   = lane & 3;           // 0..3
    const uint32_t bqbase = OB_B + h * BQ_BYTES;

    for (int i = 0; i < NKC; i++) {
        CP_WAIT1();
        __syncthreads();
        if (i + 2 < NKC) {
            int b = (i + 2) % NRING;
            for (int j = tid; j < CHUNK_BYTES / 16; j += 512)
                cp_async16(smb + OB_A + b * CHUNK_BYTES + j * 16,
                           g_Ah + (size_t)(i + 2) * CHUNK_BYTES + j * 16);
            CP_COMMIT();
        }
        const uint32_t abase = smb + OB_A + (i % NRING) * CHUNK_BYTES;

        uint32_t bf[4][2];
        #pragma unroll
        for (int nt = 0; nt < 4; nt++) {
            int n = nt * 8 + nrow;
            uint32_t bidx = bqbase + (uint32_t)(n * 648 + i * 16 + kq * 2) * 2;
            bf[nt][0] = *(const uint32_t*)(smraw + bidx);
            bf[nt][1] = *(const uint32_t*)(smraw + bidx + 16);
        }

        #pragma unroll
        for (int j = 0; j < 5; j++) {
            int mt = wl + 8 * j;
            int m = mt * 16 + (lane & 15);
            uint32_t addr = abase + m * 32 + ((((lane >> 4) ^ (m >> 2)) & 1) << 4);
            uint32_t a0, a1, a2, a3;
            ldsm_x4(a0, a1, a2, a3, addr);
            #pragma unroll
            for (int nt = 0; nt < 4; nt++)
                mma16816(acc[j][nt][0], acc[j][nt][1], acc[j][nt][2], acc[j][nt][3],
                         a0, a1, a2, a3, bf[nt][0], bf[nt][1]);
        }
    }
    CP_WAIT0();
    __syncthreads();

    // ---- per-q: store G, epilogue, outputs (serialized q0 then q1) ----
    for (int qi = 0; qi < 2; qi++) {
        const int q = q0 + qi;
        if (h == qi) {
            #pragma unroll
            for (int j = 0; j < 5; j++) {
                int mt = wl + 8 * j;
                int r0 = mt * 16 + (lane >> 2);
                int r1 = r0 + 8;
                #pragma unroll
                for (int nt = 0; nt < 4; nt++) {
                    int c = nt * 8 + (lane & 3) * 2;
                    if (c < 25) {
                        if (r0 < 625) smf[GI + r0 * 25 + c] = acc[j][nt][0];
                        if (r1 < 625) smf[GI + r1 * 25 + c] = acc[j][nt][2];
                    }
                    if (c + 1 < 25) {
                        if (r0 < 625) smf[GI + r0 * 25 + c + 1] = acc[j][nt][1];
                        if (r1 < 625) smf[GI + r1 * 25 + c + 1] = acc[j][nt][3];
                    }
                }
            }
        }
        __syncthreads();

        // per-p epilogue (all 16 warps)
        for (int p = w; p < PP; p += 16) {
            float* kn = smf + KNI + w * 112;
            if (lane < 25) {
                float a1 = 0.f, a2 = 0.f;
                int rowb = (p * 25 + lane) * 25;
                int colb = p * 25 * 25 + lane;
                #pragma unroll
                for (int j = 0; j < 25; j++) {
                    a1 += smf[GI + rowb + j];
                    a2 += smf[GI + colb + j * 25];
                }
                kn[lane]      = a1 * (1.f / 25.f);   // g1
                kn[25 + lane] = a2 * (1.f / 25.f);   // g2
            }
            __syncwarp();
            if (lane < 5) {
                float a = smf[OB_B1F/4 + lane];
                #pragma unroll
                for (int j = 0; j < 25; j++) a += kn[j] * smf[OB_W1F/4 + lane * 25 + j];
                kn[50 + lane] = fmaxf(a, 0.f);
            } else if (lane >= 8 && lane < 13) {
                int ii = lane - 8;
                float a = smf[OB_B1F/4 + ii];
                #pragma unroll
                for (int j = 0; j < 25; j++) a += kn[25 + j] * smf[OB_W1F/4 + ii * 25 + j];
                kn[55 + ii] = fmaxf(a, 0.f);
            }
            __syncwarp();
            if (lane < 25) {
                float a1 = smf[OB_B2S/4 + lane], a2 = a1;
                #pragma unroll
                for (int ii = 0; ii < 5; ii++) {
                    float wv = smf[OB_W2/4 + lane * 5 + ii];
                    a1 += kn[50 + ii] * wv;
                    a2 += kn[55 + ii] * wv;
                }
                kn[60 + lane] = fmaxf(a1, 0.f);  // k1
                kn[85 + lane] = fmaxf(a2, 0.f);  // k2
            }
            __syncwarp();
            if (lane < 25) {
                float att1 = 0.f, attt = 0.f;
                int colb = p * 25 * 25 + lane;
                int rowb = (p * 25 + lane) * 25;
                #pragma unroll
                for (int j = 0; j < 25; j++) {
                    att1 += kn[60 + j] * smf[GI + colb + j * 25];
                    attt += smf[GI + rowb + j] * kn[85 + j];
                }
                g_att1[(size_t)(p * QQ + q) * SS + lane] = att1;
                smf[ATI + p * 25 + lane] = attt;
            }
        }
        __syncthreads();

        // am softmax (warp 0) + cls softmax (warp 1), parallel
        if (w == 0) {
            float val = 0.f;
            if (lane < 25) {
                #pragma unroll
                for (int j = 0; j < 25; j++) val += smf[ATI + j * 25 + lane];
                val *= (1.f / 25.f);
            }
            float m = (lane < 25) ? val : -1e30f;
            #pragma unroll
            for (int o = 16; o; o >>= 1) m = fmaxf(m, __shfl_xor_sync(0xffffffffu, m, o));
            float e = (lane < 25) ? expf(val - m) : 0.f;
            float ssum = e;
            #pragma unroll
            for (int o = 16; o; o >>= 1) ssum += __shfl_xor_sync(0xffffffffu, ssum, o);
            float a = e / ssum;
            if (lane < 25) {
                out[OFT_AM + q * SS + lane] = a;
                smf[OB_TS/4 + lane] = a + 1.f;
            }
        } else if (w == 1) {
            float rs = 0.f;
            if (lane < 25) {
                #pragma unroll
                for (int j = 0; j < 25; j++) rs += smf[ATI + lane * 25 + j];
            }
            int g = (lane < 5) ? lane : 4;
            float cg = 0.f;
            #pragma unroll
            for (int i = 0; i < 5; i++) cg += __shfl_sync(0xffffffffu, rs, g * 5 + i);
            cg *= (1.f / 125.f);
            float m = (lane < 5) ? cg : -1e30f;
            #pragma unroll
            for (int o = 4; o; o >>= 1) m = fmaxf(m, __shfl_xor_sync(0xffffffffu, m, o));
            float e = (lane < 5) ? expf(cg - m) : 0.f;
            float ssum = e;
            #pragma unroll
            for (int o = 4; o; o >>= 1) ssum += __shfl_xor_sync(0xffffffffu, ssum, o);
            if (lane < 5) out[OFT_CLS + q * 5 + lane] = e / ssum;
        }
        __syncthreads();

        // ftest_out = raw ftest * (am + 1)
        const float4* fq4 = (const float4*)(ftest + (size_t)q * TILE);
        float4* outq = (float4*)(out + OFT_TE + (size_t)q * TILE);
        for (int i = tid; i < 4000; i += 512) {
            float4 b = fq4[i];
            int s = (i * 4) % 25;
            float4 o;
            o.x = b.x * smf[OB_TS/4 + s]; s = (s == 24) ? 0 : s + 1;
            o.y = b.y * smf[OB_TS/4 + s]; s = (s == 24) ? 0 : s + 1;
            o.z = b.z * smf[OB_TS/4 + s]; s = (s == 24) ? 0 : s + 1;
            o.w = b.w * smf[OB_TS/4 + s];
            outq[i] = o;
        }
    }
}

// ---------------- K3: reduce att1 over q, softmax, ftrain_out ----------------
__global__ void __launch_bounds__(256) cam_final_train(const float* __restrict__ ftrain,
                                                       float* __restrict__ out) {
    extern __shared__ float bins[];       // 256*25 floats
    __shared__ float att_s[SS];
    int p = blockIdx.x, tid = threadIdx.x, lane = tid & 31, w = tid >> 5;
    for (int i = 0; i < 25; i++) bins[tid * 25 + i] = 0.f;
    __syncthreads();
    const float4* a4 = (const float4*)(g_att1 + (size_t)p * QQ * SS);
    for (int jj = tid; jj < 12500; jj += 256) {
        float4 v = a4[jj];
        int s = (jj * 4) % 25;
        bins[tid * 25 + s] += v.x; s = (s == 24) ? 0 : s + 1;
        bins[tid * 25 + s] += v.y; s = (s == 24) ? 0 : s + 1;
        bins[tid * 25 + s] += v.z; s = (s == 24) ? 0 : s + 1;
        bins[tid * 25 + s] += v.w;
    }
    __syncthreads();
    for (int s = w; s < 25; s += 8) {
        float acc = 0.f;
        #pragma unroll
        for (int t = 0; t < 8; t++) acc += bins[(lane + 32 * t) * 25 + s];
        acc = warp_sum(acc);
        if (lane == 0) att_s[s] = acc * (1.f / (float)QQ);
    }
    __syncthreads();
    if (w == 0) {
        float val = (lane < 25) ? att_s[lane] : -1e30f;
        float m = val;
        #pragma unroll
        for (int o = 16; o; o >>= 1) m = fmaxf(m, __shfl_xor_sync(0xffffffffu, m, o));
        float e = (lane < 25) ? expf(val - m) : 0.f;
        float ssum = e;
        #pragma unroll
        for (int o = 16; o; o >>= 1) ssum += __shfl_xor_sync(0xffffffffu, ssum, o);
        if (lane < 25) att_s[lane] = e / ssum + 1.f;
    }
    __syncthreads();
    const float4* fp4 = (const float4*)(ftrain + p * TILE);
    float4* outp = (float4*)(out + (size_t)p * TILE);
    for (int i = tid; i < 4000; i += 256) {
        float4 b = fp4[i];
        int s = (i * 4) % 25;
        float4 o;
        o.x = b.x * att_s[s]; s = (s == 24) ? 0 : s + 1;
        o.y = b.y * att_s[s]; s = (s == 24) ? 0 : s + 1;
        o.z = b.z * att_s[s]; s = (s == 24) ? 0 : s + 1;
        o.w = b.w * att_s[s];
        outp[i] = o;
    }
}

// ---------------- launch ----------------
extern "C" void kernel_launch(void* const* d_in, const int* in_sizes, int n_in,
                              void* d_out, int out_size) {
    const float* ftrain  = (const float*)d_in[0];
    const float* ftest   = (const float*)d_in[1];
    const float* conv1_w = (const float*)d_in[6];
    const float* conv1_b = (const float*)d_in[7];
    const float* bn_gamma= (const float*)d_in[8];
    const float* bn_beta = (const float*)d_in[9];
    const float* bn_mean = (const float*)d_in[10];
    const float* bn_var  = (const float*)d_in[11];
    const float* conv2_w = (const float*)d_in[12];
    const float* conv2_b = (const float*)d_in[13];
    float* out = (float*)d_out;

    const int prep_smem  = 64128 + 32000;
    const int final_smem = 256 * 25 * 4;
    cudaFuncSetAttribute(cam_prep_A,      cudaFuncAttributeMaxDynamicSharedMemorySize, prep_smem);
    cudaFuncSetAttribute(cam_main,        cudaFuncAttributeMaxDynamicSharedMemorySize, SMEM_BYTES);
    cudaFuncSetAttribute(cam_final_train, cudaFuncAttributeMaxDynamicSharedMemorySize, final_smem);

    cam_prep_A<<<PP, 256, prep_smem>>>(ftrain);
    cam_main<<<QQ / 2, 512, SMEM_BYTES>>>(ftest, conv1_w, conv1_b, bn_gamma, bn_beta,
                                          bn_mean, bn_var, conv2_w, conv2_b, out);
    cam_final_train<<<PP, 256, final_smem>>>(ftrain, out);
}